// round 1
// baseline (speedup 1.0000x reference)
#include <cuda_runtime.h>

#define N_DIS 25000
#define N_MIR 25000
#define NTOT  50000
#define EMB   128
#define EDGES 600000

// Scratch (device globals: no allocation allowed)
__device__ float g_h   [NTOT * EMB];   // embeddings after per-type projection
__device__ float g_h1  [NTOT * EMB];   // layer-1 output
__device__ float g_agg1[NTOT * EMB];   // segment-sum buffer layer 1
__device__ float g_agg2[NTOT * EMB];   // segment-sum buffer layer 2
__device__ float g_deg [NTOT];
__device__ float g_inv [NTOT];

// ---------------------------------------------------------------------------
// Zero scratch accumulators (runs at the head of every launch -> replay-safe)
// ---------------------------------------------------------------------------
__global__ void zero_kernel() {
    int i = blockIdx.x * blockDim.x + threadIdx.x;
    if (i < NTOT * EMB) {
        g_agg1[i] = 0.0f;
        g_agg2[i] = 0.0f;
    }
    if (i < NTOT) g_deg[i] = 0.0f;
}

// ---------------------------------------------------------------------------
// Degree + inverse degree
// ---------------------------------------------------------------------------
__global__ void degree_kernel(const int* __restrict__ dst) {
    int e = blockIdx.x * blockDim.x + threadIdx.x;
    if (e < EDGES) atomicAdd(&g_deg[dst[e]], 1.0f);
}

__global__ void invdeg_kernel() {
    int i = blockIdx.x * blockDim.x + threadIdx.x;
    if (i < NTOT) g_inv[i] = 1.0f / fmaxf(g_deg[i], 1.0f);
}

// ---------------------------------------------------------------------------
// Edge aggregation: one warp per edge, float4 gather + 4 scalar atomics/lane
// ---------------------------------------------------------------------------
__global__ void aggregate_kernel(const int* __restrict__ src,
                                 const int* __restrict__ dst,
                                 const float* __restrict__ X,
                                 float* __restrict__ AGG) {
    int gtid = blockIdx.x * blockDim.x + threadIdx.x;
    int edge = gtid >> 5;
    int lane = gtid & 31;
    if (edge >= EDGES) return;
    int s = src[edge];
    int d = dst[edge];
    float4 v = ((const float4*)(X + (size_t)s * EMB))[lane];
    float* a = AGG + (size_t)d * EMB + lane * 4;
    atomicAdd(a + 0, v.x);
    atomicAdd(a + 1, v.y);
    atomicAdd(a + 2, v.z);
    atomicAdd(a + 3, v.w);
}

// ---------------------------------------------------------------------------
// Tiled fp32 GEMM with fixed N=128 output width.
//   C[M,128] = A[M,K] @ W[K,128]  (+ optional (A2*rowscale)[M,128] @ W2)  + b
// BM=64 rows/block, BK=16, 256 threads, each thread: 8 rows x 4 cols.
// ---------------------------------------------------------------------------
#define BM 64
#define BK 16

__global__ __launch_bounds__(256)
void gemm128(const float* __restrict__ A, int M, int K,
             const float* __restrict__ W,
             const float* __restrict__ bias,
             const float* __restrict__ A2,        // optional (K2 = 128)
             const float* __restrict__ W2,
             const float* __restrict__ rowscale,  // applied to A2 rows
             float* __restrict__ C,
             int relu) {
    __shared__ float As[BM][BK];
    __shared__ float Ws[BK][EMB];

    const int tid  = threadIdx.x;
    const int row0 = blockIdx.x * BM;
    const int trow = tid >> 5;  // 0..7  (constant within a warp -> LDS broadcast)
    const int tcol = tid & 31;  // 0..31 (float4 column group)

    float acc[8][4];
#pragma unroll
    for (int r = 0; r < 8; ++r)
#pragma unroll
        for (int c = 0; c < 4; ++c) acc[r][c] = 0.0f;

    for (int pass = 0; pass < 2; ++pass) {
        const float* Ap;
        const float* Wp;
        const float* scl;
        int Kp;
        if (pass == 0) {
            Ap = A; Wp = W; Kp = K; scl = nullptr;
        } else {
            if (A2 == nullptr) break;
            Ap = A2; Wp = W2; Kp = EMB; scl = rowscale;
        }

        for (int k0 = 0; k0 < Kp; k0 += BK) {
            // A tile: 64 rows x 16 k (coalesced: consecutive tid -> consecutive k)
            for (int idx = tid; idx < BM * BK; idx += 256) {
                int r  = idx >> 4;
                int k  = idx & 15;
                int gr = row0 + r;
                int gk = k0 + k;
                float v = 0.0f;
                if (gr < M && gk < Kp) {
                    v = Ap[(size_t)gr * Kp + gk];
                    if (scl) v *= scl[gr];
                }
                As[r][k] = v;
            }
            // W tile: 16 k x 128 n (fully coalesced over n)
            for (int idx = tid; idx < BK * EMB; idx += 256) {
                int k  = idx >> 7;
                int n  = idx & 127;
                int gk = k0 + k;
                Ws[k][n] = (gk < Kp) ? Wp[(size_t)gk * EMB + n] : 0.0f;
            }
            __syncthreads();

#pragma unroll
            for (int kk = 0; kk < BK; ++kk) {
                float a[8];
#pragma unroll
                for (int r = 0; r < 8; ++r) a[r] = As[trow * 8 + r][kk];
                float4 w = ((const float4*)Ws[kk])[tcol];
#pragma unroll
                for (int r = 0; r < 8; ++r) {
                    acc[r][0] += a[r] * w.x;
                    acc[r][1] += a[r] * w.y;
                    acc[r][2] += a[r] * w.z;
                    acc[r][3] += a[r] * w.w;
                }
            }
            __syncthreads();
        }
    }

    float4 b4 = ((const float4*)bias)[tcol];
#pragma unroll
    for (int r = 0; r < 8; ++r) {
        int gr = row0 + trow * 8 + r;
        if (gr < M) {
            float4 o;
            o.x = acc[r][0] + b4.x;
            o.y = acc[r][1] + b4.y;
            o.z = acc[r][2] + b4.z;
            o.w = acc[r][3] + b4.w;
            if (relu) {
                o.x = fmaxf(o.x, 0.0f);
                o.y = fmaxf(o.y, 0.0f);
                o.z = fmaxf(o.z, 0.0f);
                o.w = fmaxf(o.w, 0.0f);
            }
            ((float4*)(C + (size_t)gr * EMB))[tcol] = o;
        }
    }
}

// ---------------------------------------------------------------------------
// Launch
// ---------------------------------------------------------------------------
extern "C" void kernel_launch(void* const* d_in, const int* in_sizes, int n_in,
                              void* d_out, int out_size) {
    const float* d_feat = (const float*)d_in[0];   // [25000, 383]
    const float* m_feat = (const float*)d_in[1];   // [25000, 495]
    const int*   src    = (const int*)d_in[2];     // [600000]
    const int*   dst    = (const int*)d_in[3];     // [600000]
    const float* W_d    = (const float*)d_in[4];   // [383, 128]
    const float* b_d    = (const float*)d_in[5];   // [128]
    const float* W_m    = (const float*)d_in[6];   // [495, 128]
    const float* b_m    = (const float*)d_in[7];   // [128]
    const float* W_s1   = (const float*)d_in[8];   // [128, 128]
    const float* W_n1   = (const float*)d_in[9];
    const float* b1     = (const float*)d_in[10];
    const float* W_s2   = (const float*)d_in[11];
    const float* W_n2   = (const float*)d_in[12];
    const float* b2     = (const float*)d_in[13];
    float* out = (float*)d_out;                    // [50000, 128]

    float *h, *h1, *agg1, *agg2, *inv;
    {
        void* p;
        cudaGetSymbolAddress(&p, g_h);    h    = (float*)p;
        cudaGetSymbolAddress(&p, g_h1);   h1   = (float*)p;
        cudaGetSymbolAddress(&p, g_agg1); agg1 = (float*)p;
        cudaGetSymbolAddress(&p, g_agg2); agg2 = (float*)p;
        cudaGetSymbolAddress(&p, g_inv);  inv  = (float*)p;
    }

    // 1) zero accumulators + degree
    zero_kernel<<<(NTOT * EMB + 255) / 256, 256>>>();

    // 2) per-type embedding projections into h
    gemm128<<<(N_DIS + BM - 1) / BM, 256>>>(d_feat, N_DIS, 383, W_d, b_d,
                                            nullptr, nullptr, nullptr, h, 0);
    gemm128<<<(N_MIR + BM - 1) / BM, 256>>>(m_feat, N_MIR, 495, W_m, b_m,
                                            nullptr, nullptr, nullptr,
                                            h + (size_t)N_DIS * EMB, 0);

    // 3) degrees
    degree_kernel<<<(EDGES + 255) / 256, 256>>>(dst);
    invdeg_kernel<<<(NTOT + 255) / 256, 256>>>();

    // 4) layer 1: aggregate h -> agg1, then combine (relu)
    {
        int warps_total = EDGES;            // 1 warp per edge
        int blocks = (warps_total * 32 + 255) / 256;
        aggregate_kernel<<<blocks, 256>>>(src, dst, h, agg1);
    }
    gemm128<<<(NTOT + BM - 1) / BM, 256>>>(h, NTOT, EMB, W_s1, b1,
                                           agg1, W_n1, inv, h1, 1);

    // 5) layer 2: aggregate h1 -> agg2, then combine (no relu) -> d_out
    {
        int blocks = (EDGES * 32 + 255) / 256;
        aggregate_kernel<<<blocks, 256>>>(src, dst, h1, agg2);
    }
    gemm128<<<(NTOT + BM - 1) / BM, 256>>>(h1, NTOT, EMB, W_s2, b2,
                                           agg2, W_n2, inv, out, 0);
}

// round 2
// speedup vs baseline: 1.4588x; 1.4588x over previous
#include <cuda_runtime.h>

#define N_DIS 25000
#define N_MIR 25000
#define NTOT  50000
#define EMB   128
#define EDGES 600000

// Scratch (device globals: no allocation allowed)
__device__ float g_h   [NTOT * EMB];
__device__ float g_h1  [NTOT * EMB];
__device__ float g_agg1[NTOT * EMB];
__device__ float g_agg2[NTOT * EMB];
__device__ int   g_degi[NTOT];
__device__ float g_inv [NTOT];
__device__ int   g_rowptr[NTOT + 1];
__device__ int   g_cursor[NTOT];
__device__ int   g_esrc[EDGES];      // src node id per CSR slot (grouped by dst)

// ---------------------------------------------------------------------------
// Zero the degree histogram (only thing needing re-init per replay)
// ---------------------------------------------------------------------------
__global__ void zero_deg_kernel() {
    int i = blockIdx.x * blockDim.x + threadIdx.x;
    if (i < NTOT) g_degi[i] = 0;
}

__global__ void degree_kernel(const int* __restrict__ dst) {
    int e = blockIdx.x * blockDim.x + threadIdx.x;
    if (e < EDGES) atomicAdd(&g_degi[dst[e]], 1);
}

// ---------------------------------------------------------------------------
// Single-block exclusive scan of degrees -> row_ptr, cursor, inv_deg
// ---------------------------------------------------------------------------
__global__ void scan_kernel() {
    __shared__ int wsum[32];
    __shared__ int carry_s;
    const int t = threadIdx.x;            // 1024 threads
    if (t == 0) carry_s = 0;
    __syncthreads();

    for (int base = 0; base < NTOT; base += 1024) {
        int i = base + t;
        int v = (i < NTOT) ? g_degi[i] : 0;
        // inclusive warp scan
        int x = v;
#pragma unroll
        for (int o = 1; o < 32; o <<= 1) {
            int y = __shfl_up_sync(0xffffffffu, x, o);
            if ((t & 31) >= o) x += y;
        }
        if ((t & 31) == 31) wsum[t >> 5] = x;
        __syncthreads();
        if (t < 32) {
            int s = wsum[t];
#pragma unroll
            for (int o = 1; o < 32; o <<= 1) {
                int y = __shfl_up_sync(0xffffffffu, s, o);
                if (t >= o) s += y;
            }
            wsum[t] = s;
        }
        __syncthreads();
        int warpoff = (t >= 32) ? wsum[(t >> 5) - 1] : 0;
        int excl = carry_s + warpoff + x - v;
        if (i < NTOT) {
            g_rowptr[i] = excl;
            g_cursor[i] = excl;
            g_inv[i] = 1.0f / fmaxf((float)v, 1.0f);
        }
        __syncthreads();
        if (t == 0) carry_s += wsum[31];
        __syncthreads();
    }
    if (t == 0) g_rowptr[NTOT] = carry_s;
}

__global__ void scatter_kernel(const int* __restrict__ src,
                               const int* __restrict__ dst) {
    int e = blockIdx.x * blockDim.x + threadIdx.x;
    if (e < EDGES) {
        int d = dst[e];
        int pos = atomicAdd(&g_cursor[d], 1);
        g_esrc[pos] = src[e];
    }
}

// ---------------------------------------------------------------------------
// CSR mean-aggregation: one warp per dst node. Pure gather, no atomics.
// AGG[n] = inv_deg[n] * sum_{e in CSR[n]} X[esrc[e]]
// ---------------------------------------------------------------------------
__global__ __launch_bounds__(256)
void aggregate_csr_kernel(const float* __restrict__ X,
                          float* __restrict__ AGG) {
    int warp = (blockIdx.x * blockDim.x + threadIdx.x) >> 5;
    int lane = threadIdx.x & 31;
    if (warp >= NTOT) return;

    int beg = g_rowptr[warp];
    int end = g_rowptr[warp + 1];
    float inv = g_inv[warp];

    float4 acc = make_float4(0.f, 0.f, 0.f, 0.f);

    int e = beg;
    for (; e + 4 <= end; e += 4) {
        int s0 = g_esrc[e + 0];
        int s1 = g_esrc[e + 1];
        int s2 = g_esrc[e + 2];
        int s3 = g_esrc[e + 3];
        float4 v0 = ((const float4*)(X + (size_t)s0 * EMB))[lane];
        float4 v1 = ((const float4*)(X + (size_t)s1 * EMB))[lane];
        float4 v2 = ((const float4*)(X + (size_t)s2 * EMB))[lane];
        float4 v3 = ((const float4*)(X + (size_t)s3 * EMB))[lane];
        acc.x += v0.x + v1.x + v2.x + v3.x;
        acc.y += v0.y + v1.y + v2.y + v3.y;
        acc.z += v0.z + v1.z + v2.z + v3.z;
        acc.w += v0.w + v1.w + v2.w + v3.w;
    }
    for (; e < end; ++e) {
        int s = g_esrc[e];
        float4 v = ((const float4*)(X + (size_t)s * EMB))[lane];
        acc.x += v.x; acc.y += v.y; acc.z += v.z; acc.w += v.w;
    }

    acc.x *= inv; acc.y *= inv; acc.z *= inv; acc.w *= inv;
    ((float4*)(AGG + (size_t)warp * EMB))[lane] = acc;
}

// ---------------------------------------------------------------------------
// Tiled fp32 GEMM, N fixed at 128.
//   C[M,128] = A[M,K] @ W[K,128] (+ A2[M,128] @ W2) + b   [optional relu]
// BM=128 rows/block, BK=16, 256 threads, 8 rows x 8 cols per thread.
// Thread (ty,tx) = (tid/16, tid%16); cols = {tx*4..+3, 64+tx*4..+3}.
// ---------------------------------------------------------------------------
#define BM 128
#define BK 16

__global__ __launch_bounds__(256)
void gemm128(const float* __restrict__ A, int M, int K,
             const float* __restrict__ W,
             const float* __restrict__ bias,
             const float* __restrict__ A2,        // optional, K2 = 128
             const float* __restrict__ W2,
             float* __restrict__ C,
             int relu) {
    __shared__ float As[BM][BK + 1];
    __shared__ float Ws[BK][EMB];

    const int tid  = threadIdx.x;
    const int row0 = blockIdx.x * BM;
    const int ty   = tid >> 4;    // 0..15
    const int tx   = tid & 15;    // 0..15

    float acc[8][8];
#pragma unroll
    for (int r = 0; r < 8; ++r)
#pragma unroll
        for (int c = 0; c < 8; ++c) acc[r][c] = 0.0f;

    for (int pass = 0; pass < 2; ++pass) {
        const float* Ap;
        const float* Wp;
        int Kp;
        if (pass == 0) {
            Ap = A; Wp = W; Kp = K;
        } else {
            if (A2 == nullptr) break;
            Ap = A2; Wp = W2; Kp = EMB;
        }

        for (int k0 = 0; k0 < Kp; k0 += BK) {
            // A tile: 128 rows x 16 k
#pragma unroll
            for (int i = 0; i < (BM * BK) / 256; ++i) {
                int idx = tid + i * 256;
                int r  = idx >> 4;
                int k  = idx & 15;
                int gr = row0 + r;
                int gk = k0 + k;
                float v = 0.0f;
                if (gr < M && gk < Kp) v = Ap[(size_t)gr * Kp + gk];
                As[r][k] = v;
            }
            // W tile: 16 k x 128 n
#pragma unroll
            for (int i = 0; i < (BK * EMB) / 256; ++i) {
                int idx = tid + i * 256;
                int k  = idx >> 7;
                int n  = idx & 127;
                int gk = k0 + k;
                Ws[k][n] = (gk < Kp) ? Wp[(size_t)gk * EMB + n] : 0.0f;
            }
            __syncthreads();

#pragma unroll
            for (int kk = 0; kk < BK; ++kk) {
                float a[8];
#pragma unroll
                for (int r = 0; r < 8; ++r) a[r] = As[ty * 8 + r][kk];
                float4 w0 = *(const float4*)&Ws[kk][tx * 4];
                float4 w1 = *(const float4*)&Ws[kk][64 + tx * 4];
#pragma unroll
                for (int r = 0; r < 8; ++r) {
                    acc[r][0] += a[r] * w0.x;
                    acc[r][1] += a[r] * w0.y;
                    acc[r][2] += a[r] * w0.z;
                    acc[r][3] += a[r] * w0.w;
                    acc[r][4] += a[r] * w1.x;
                    acc[r][5] += a[r] * w1.y;
                    acc[r][6] += a[r] * w1.z;
                    acc[r][7] += a[r] * w1.w;
                }
            }
            __syncthreads();
        }
    }

    float4 b0 = *(const float4*)&bias[tx * 4];
    float4 b1 = *(const float4*)&bias[64 + tx * 4];
#pragma unroll
    for (int r = 0; r < 8; ++r) {
        int gr = row0 + ty * 8 + r;
        if (gr < M) {
            float4 o0, o1;
            o0.x = acc[r][0] + b0.x;  o0.y = acc[r][1] + b0.y;
            o0.z = acc[r][2] + b0.z;  o0.w = acc[r][3] + b0.w;
            o1.x = acc[r][4] + b1.x;  o1.y = acc[r][5] + b1.y;
            o1.z = acc[r][6] + b1.z;  o1.w = acc[r][7] + b1.w;
            if (relu) {
                o0.x = fmaxf(o0.x, 0.f); o0.y = fmaxf(o0.y, 0.f);
                o0.z = fmaxf(o0.z, 0.f); o0.w = fmaxf(o0.w, 0.f);
                o1.x = fmaxf(o1.x, 0.f); o1.y = fmaxf(o1.y, 0.f);
                o1.z = fmaxf(o1.z, 0.f); o1.w = fmaxf(o1.w, 0.f);
            }
            *(float4*)&C[(size_t)gr * EMB + tx * 4]      = o0;
            *(float4*)&C[(size_t)gr * EMB + 64 + tx * 4] = o1;
        }
    }
}

// ---------------------------------------------------------------------------
// Launch
// ---------------------------------------------------------------------------
extern "C" void kernel_launch(void* const* d_in, const int* in_sizes, int n_in,
                              void* d_out, int out_size) {
    const float* d_feat = (const float*)d_in[0];   // [25000, 383]
    const float* m_feat = (const float*)d_in[1];   // [25000, 495]
    const int*   src    = (const int*)d_in[2];     // [600000]
    const int*   dst    = (const int*)d_in[3];     // [600000]
    const float* W_d    = (const float*)d_in[4];
    const float* b_d    = (const float*)d_in[5];
    const float* W_m    = (const float*)d_in[6];
    const float* b_m    = (const float*)d_in[7];
    const float* W_s1   = (const float*)d_in[8];
    const float* W_n1   = (const float*)d_in[9];
    const float* b1     = (const float*)d_in[10];
    const float* W_s2   = (const float*)d_in[11];
    const float* W_n2   = (const float*)d_in[12];
    const float* b2     = (const float*)d_in[13];
    float* out = (float*)d_out;                    // [50000, 128]

    float *h, *h1, *agg1, *agg2;
    {
        void* p;
        cudaGetSymbolAddress(&p, g_h);    h    = (float*)p;
        cudaGetSymbolAddress(&p, g_h1);   h1   = (float*)p;
        cudaGetSymbolAddress(&p, g_agg1); agg1 = (float*)p;
        cudaGetSymbolAddress(&p, g_agg2); agg2 = (float*)p;
    }

    // CSR build
    zero_deg_kernel<<<(NTOT + 255) / 256, 256>>>();
    degree_kernel<<<(EDGES + 255) / 256, 256>>>(dst);
    scan_kernel<<<1, 1024>>>();
    scatter_kernel<<<(EDGES + 255) / 256, 256>>>(src, dst);

    // Per-type embedding projections into h
    gemm128<<<(N_DIS + BM - 1) / BM, 256>>>(d_feat, N_DIS, 383, W_d, b_d,
                                            nullptr, nullptr, h, 0);
    gemm128<<<(N_MIR + BM - 1) / BM, 256>>>(m_feat, N_MIR, 495, W_m, b_m,
                                            nullptr, nullptr,
                                            h + (size_t)N_DIS * EMB, 0);

    // Layer 1
    aggregate_csr_kernel<<<(NTOT * 32 + 255) / 256, 256>>>(h, agg1);
    gemm128<<<(NTOT + BM - 1) / BM, 256>>>(h, NTOT, EMB, W_s1, b1,
                                           agg1, W_n1, h1, 1);

    // Layer 2
    aggregate_csr_kernel<<<(NTOT * 32 + 255) / 256, 256>>>(h1, agg2);
    gemm128<<<(NTOT + BM - 1) / BM, 256>>>(h1, NTOT, EMB, W_s2, b2,
                                           agg2, W_n2, out, 0);
}

// round 3
// speedup vs baseline: 2.4307x; 1.6663x over previous
#include <cuda_runtime.h>
#include <cstdint>

#define N_DIS 25000
#define N_MIR 25000
#define NTOT  50000
#define EMB   128
#define EDGES 600000

// Scratch (device globals: no allocation allowed)
__device__ float g_h   [NTOT * EMB];
__device__ float g_h1  [NTOT * EMB];
__device__ float g_agg1[NTOT * EMB];
__device__ float g_agg2[NTOT * EMB];
__device__ int   g_degi[NTOT];
__device__ float g_inv [NTOT];
__device__ int   g_rowptr[NTOT + 1];
__device__ int   g_cursor[NTOT];
__device__ int   g_esrc[EDGES];      // src node id per CSR slot (grouped by dst)

// ---------------------------------------------------------------------------
// CSR build
// ---------------------------------------------------------------------------
__global__ void zero_deg_kernel() {
    int i = blockIdx.x * blockDim.x + threadIdx.x;
    if (i < NTOT) g_degi[i] = 0;
}

__global__ void degree_kernel(const int* __restrict__ dst) {
    int e = blockIdx.x * blockDim.x + threadIdx.x;
    if (e < EDGES) atomicAdd(&g_degi[dst[e]], 1);
}

__global__ void scan_kernel() {
    __shared__ int wsum[32];
    __shared__ int carry_s;
    const int t = threadIdx.x;            // 1024 threads
    if (t == 0) carry_s = 0;
    __syncthreads();

    for (int base = 0; base < NTOT; base += 1024) {
        int i = base + t;
        int v = (i < NTOT) ? g_degi[i] : 0;
        int x = v;
#pragma unroll
        for (int o = 1; o < 32; o <<= 1) {
            int y = __shfl_up_sync(0xffffffffu, x, o);
            if ((t & 31) >= o) x += y;
        }
        if ((t & 31) == 31) wsum[t >> 5] = x;
        __syncthreads();
        if (t < 32) {
            int s = wsum[t];
#pragma unroll
            for (int o = 1; o < 32; o <<= 1) {
                int y = __shfl_up_sync(0xffffffffu, s, o);
                if (t >= o) s += y;
            }
            wsum[t] = s;
        }
        __syncthreads();
        int warpoff = (t >= 32) ? wsum[(t >> 5) - 1] : 0;
        int excl = carry_s + warpoff + x - v;
        if (i < NTOT) {
            g_rowptr[i] = excl;
            g_cursor[i] = excl;
            g_inv[i] = 1.0f / fmaxf((float)v, 1.0f);
        }
        __syncthreads();
        if (t == 0) carry_s += wsum[31];
        __syncthreads();
    }
    if (t == 0) g_rowptr[NTOT] = carry_s;
}

__global__ void scatter_kernel(const int* __restrict__ src,
                               const int* __restrict__ dst) {
    int e = blockIdx.x * blockDim.x + threadIdx.x;
    if (e < EDGES) {
        int d = dst[e];
        int pos = atomicAdd(&g_cursor[d], 1);
        g_esrc[pos] = src[e];
    }
}

// ---------------------------------------------------------------------------
// CSR mean-aggregation: one warp per dst node. Pure gather, no atomics.
// ---------------------------------------------------------------------------
__global__ __launch_bounds__(256)
void aggregate_csr_kernel(const float* __restrict__ X,
                          float* __restrict__ AGG) {
    int warp = (blockIdx.x * blockDim.x + threadIdx.x) >> 5;
    int lane = threadIdx.x & 31;
    if (warp >= NTOT) return;

    int beg = g_rowptr[warp];
    int end = g_rowptr[warp + 1];
    float inv = g_inv[warp];

    float4 acc = make_float4(0.f, 0.f, 0.f, 0.f);

    int e = beg;
    for (; e + 4 <= end; e += 4) {
        int s0 = g_esrc[e + 0];
        int s1 = g_esrc[e + 1];
        int s2 = g_esrc[e + 2];
        int s3 = g_esrc[e + 3];
        float4 v0 = ((const float4*)(X + (size_t)s0 * EMB))[lane];
        float4 v1 = ((const float4*)(X + (size_t)s1 * EMB))[lane];
        float4 v2 = ((const float4*)(X + (size_t)s2 * EMB))[lane];
        float4 v3 = ((const float4*)(X + (size_t)s3 * EMB))[lane];
        acc.x += v0.x + v1.x + v2.x + v3.x;
        acc.y += v0.y + v1.y + v2.y + v3.y;
        acc.z += v0.z + v1.z + v2.z + v3.z;
        acc.w += v0.w + v1.w + v2.w + v3.w;
    }
    for (; e < end; ++e) {
        int s = g_esrc[e];
        float4 v = ((const float4*)(X + (size_t)s * EMB))[lane];
        acc.x += v.x; acc.y += v.y; acc.z += v.z; acc.w += v.w;
    }

    acc.x *= inv; acc.y *= inv; acc.z *= inv; acc.w *= inv;
    ((float4*)(AGG + (size_t)warp * EMB))[lane] = acc;
}

// ---------------------------------------------------------------------------
// TF32 tensor-core GEMM, N fixed at 128.
//   C[M,128] = A[M,K] @ W[K,128] (+ A2[M,128] @ W2) + b   [optional relu]
// Block tile 128x128, BK=32, 256 threads = 8 warps (2 in M x 4 in N).
// Warp tile 64x32 = 4x4 mma(m16n8k8) tiles. fp32 accumulate.
// ---------------------------------------------------------------------------
#define BM 128
#define BK 32
#define AS_LD 36     // pad: (36*r + c) % 32 = (4r + c) % 32 -> conflict-free frags
#define BS_LD 136    // pad: (136*k + n) % 32 = (8k + n) % 32 -> conflict-free frags

__device__ __forceinline__ uint32_t f2tf32(float f) {
    uint32_t u;
    asm("cvt.rna.tf32.f32 %0, %1;" : "=r"(u) : "f"(f));
    return u;
}

__device__ __forceinline__ void mma_tf32(float* d, const uint32_t* a,
                                         const uint32_t* b) {
    asm volatile(
        "mma.sync.aligned.m16n8k8.row.col.f32.tf32.tf32.f32 "
        "{%0,%1,%2,%3}, {%4,%5,%6,%7}, {%8,%9}, {%0,%1,%2,%3};\n"
        : "+f"(d[0]), "+f"(d[1]), "+f"(d[2]), "+f"(d[3])
        : "r"(a[0]), "r"(a[1]), "r"(a[2]), "r"(a[3]), "r"(b[0]), "r"(b[1]));
}

__global__ __launch_bounds__(256)
void gemm128_tc(const float* __restrict__ A, int M, int K,
                const float* __restrict__ W,
                const float* __restrict__ bias,
                const float* __restrict__ A2,   // optional, K2 = 128
                const float* __restrict__ W2,
                float* __restrict__ C,
                int relu) {
    __shared__ uint32_t As[BM][AS_LD];
    __shared__ uint32_t Bs[BK][BS_LD];

    const int tid  = threadIdx.x;
    const int lane = tid & 31;
    const int wid  = tid >> 5;
    const int wm   = wid & 1;      // 0..1  (64-row slab)
    const int wn   = wid >> 1;     // 0..3  (32-col slab)
    const int gid  = lane >> 2;    // 0..7
    const int tig  = lane & 3;     // 0..3
    const int row0 = blockIdx.x * BM;

    float acc[4][4][4];
#pragma unroll
    for (int i = 0; i < 4; ++i)
#pragma unroll
        for (int j = 0; j < 4; ++j)
#pragma unroll
            for (int c = 0; c < 4; ++c) acc[i][j][c] = 0.0f;

    for (int pass = 0; pass < 2; ++pass) {
        const float* Ap;
        const float* Wp;
        int Kp;
        if (pass == 0) {
            Ap = A; Wp = W; Kp = K;
        } else {
            if (A2 == nullptr) break;
            Ap = A2; Wp = W2; Kp = EMB;
        }
        const bool vecA = ((Kp & 3) == 0);   // float4-safe A rows (K=128 layers)

        for (int k0 = 0; k0 < Kp; k0 += BK) {
            // --- A tile: 128 rows x 32 k ---
            if (vecA) {
#pragma unroll
                for (int it = 0; it < (BM * BK / 4) / 256; ++it) {   // 4 iters
                    int idx = tid + it * 256;
                    int r  = idx >> 3;          // 0..127
                    int cg = idx & 7;           // float4 group 0..7
                    int gr = row0 + r;
                    int gk = k0 + cg * 4;
                    uint4 o;
                    if (gr < M && gk + 3 < Kp) {
                        float4 v = *(const float4*)(Ap + (size_t)gr * Kp + gk);
                        o.x = f2tf32(v.x); o.y = f2tf32(v.y);
                        o.z = f2tf32(v.z); o.w = f2tf32(v.w);
                    } else {
                        o = make_uint4(0u, 0u, 0u, 0u);
                    }
                    *(uint4*)&As[r][cg * 4] = o;
                }
            } else {
#pragma unroll
                for (int it = 0; it < (BM * BK) / 256; ++it) {       // 16 iters
                    int idx = tid + it * 256;
                    int r = idx >> 5;           // 0..127
                    int c = idx & 31;           // 0..31
                    int gr = row0 + r;
                    int gk = k0 + c;
                    uint32_t u = 0u;
                    if (gr < M && gk < Kp) u = f2tf32(Ap[(size_t)gr * Kp + gk]);
                    As[r][c] = u;
                }
            }
            // --- B tile: 32 k x 128 n (W row-major, rows are 16B-aligned) ---
#pragma unroll
            for (int it = 0; it < (BK * EMB / 4) / 256; ++it) {      // 4 iters
                int idx = tid + it * 256;
                int kk = idx >> 5;              // 0..31
                int cg = idx & 31;              // 0..31 (float4 group)
                int gk = k0 + kk;
                uint4 o;
                if (gk < Kp) {
                    float4 v = *(const float4*)(Wp + (size_t)gk * EMB + cg * 4);
                    o.x = f2tf32(v.x); o.y = f2tf32(v.y);
                    o.z = f2tf32(v.z); o.w = f2tf32(v.w);
                } else {
                    o = make_uint4(0u, 0u, 0u, 0u);
                }
                *(uint4*)&Bs[kk][cg * 4] = o;
            }
            __syncthreads();

            // --- 4 x k8 steps ---
#pragma unroll
            for (int ks = 0; ks < 4; ++ks) {
                const int kb = ks * 8;
                uint32_t af[4][4];
                uint32_t bf[4][2];
#pragma unroll
                for (int i = 0; i < 4; ++i) {
                    int r = wm * 64 + i * 16 + gid;
                    af[i][0] = As[r][kb + tig];
                    af[i][1] = As[r + 8][kb + tig];
                    af[i][2] = As[r][kb + tig + 4];
                    af[i][3] = As[r + 8][kb + tig + 4];
                }
#pragma unroll
                for (int j = 0; j < 4; ++j) {
                    int n = wn * 32 + j * 8 + gid;
                    bf[j][0] = Bs[kb + tig][n];
                    bf[j][1] = Bs[kb + tig + 4][n];
                }
#pragma unroll
                for (int i = 0; i < 4; ++i)
#pragma unroll
                    for (int j = 0; j < 4; ++j)
                        mma_tf32(acc[i][j], af[i], bf[j]);
            }
            __syncthreads();
        }
    }

    // --- epilogue: bias (+relu), write float2 pairs ---
#pragma unroll
    for (int i = 0; i < 4; ++i) {
        int r0g = row0 + wm * 64 + i * 16 + gid;
#pragma unroll
        for (int j = 0; j < 4; ++j) {
            int col = wn * 32 + j * 8 + 2 * tig;
            float bx = bias[col];
            float by = bias[col + 1];
            float2 o0, o1;
            o0.x = acc[i][j][0] + bx;  o0.y = acc[i][j][1] + by;
            o1.x = acc[i][j][2] + bx;  o1.y = acc[i][j][3] + by;
            if (relu) {
                o0.x = fmaxf(o0.x, 0.f); o0.y = fmaxf(o0.y, 0.f);
                o1.x = fmaxf(o1.x, 0.f); o1.y = fmaxf(o1.y, 0.f);
            }
            if (r0g < M)     *(float2*)&C[(size_t)r0g * EMB + col]       = o0;
            if (r0g + 8 < M) *(float2*)&C[(size_t)(r0g + 8) * EMB + col] = o1;
        }
    }
}

// ---------------------------------------------------------------------------
// Launch
// ---------------------------------------------------------------------------
extern "C" void kernel_launch(void* const* d_in, const int* in_sizes, int n_in,
                              void* d_out, int out_size) {
    const float* d_feat = (const float*)d_in[0];   // [25000, 383]
    const float* m_feat = (const float*)d_in[1];   // [25000, 495]
    const int*   src    = (const int*)d_in[2];     // [600000]
    const int*   dst    = (const int*)d_in[3];     // [600000]
    const float* W_d    = (const float*)d_in[4];
    const float* b_d    = (const float*)d_in[5];
    const float* W_m    = (const float*)d_in[6];
    const float* b_m    = (const float*)d_in[7];
    const float* W_s1   = (const float*)d_in[8];
    const float* W_n1   = (const float*)d_in[9];
    const float* b1     = (const float*)d_in[10];
    const float* W_s2   = (const float*)d_in[11];
    const float* W_n2   = (const float*)d_in[12];
    const float* b2     = (const float*)d_in[13];
    float* out = (float*)d_out;                    // [50000, 128]

    float *h, *h1, *agg1, *agg2;
    {
        void* p;
        cudaGetSymbolAddress(&p, g_h);    h    = (float*)p;
        cudaGetSymbolAddress(&p, g_h1);   h1   = (float*)p;
        cudaGetSymbolAddress(&p, g_agg1); agg1 = (float*)p;
        cudaGetSymbolAddress(&p, g_agg2); agg2 = (float*)p;
    }

    // CSR build
    zero_deg_kernel<<<(NTOT + 255) / 256, 256>>>();
    degree_kernel<<<(EDGES + 255) / 256, 256>>>(dst);
    scan_kernel<<<1, 1024>>>();
    scatter_kernel<<<(EDGES + 255) / 256, 256>>>(src, dst);

    // Per-type embedding projections into h
    gemm128_tc<<<(N_DIS + BM - 1) / BM, 256>>>(d_feat, N_DIS, 383, W_d, b_d,
                                               nullptr, nullptr, h, 0);
    gemm128_tc<<<(N_MIR + BM - 1) / BM, 256>>>(m_feat, N_MIR, 495, W_m, b_m,
                                               nullptr, nullptr,
                                               h + (size_t)N_DIS * EMB, 0);

    // Layer 1
    aggregate_csr_kernel<<<(NTOT * 32 + 255) / 256, 256>>>(h, agg1);
    gemm128_tc<<<(NTOT + BM - 1) / BM, 256>>>(h, NTOT, EMB, W_s1, b1,
                                              agg1, W_n1, h1, 1);

    // Layer 2
    aggregate_csr_kernel<<<(NTOT * 32 + 255) / 256, 256>>>(h1, agg2);
    gemm128_tc<<<(NTOT + BM - 1) / BM, 256>>>(h1, NTOT, EMB, W_s2, b2,
                                              agg2, W_n2, out, 0);
}